// round 1
// baseline (speedup 1.0000x reference)
#include <cuda_runtime.h>
#include <cuda_bf16.h>
#include <cstdint>
#include <cstddef>

// Problem dims (fixed for this problem id)
#define T_STEPS 100
#define BATCH   256
#define IN_DIM  784
#define HID     1024
#define OUT_DIM 10
#define MROWS   (T_STEPS * BATCH)        // 25600
#define BH      (BATCH * HID)            // 262144
#define BO      (BATCH * OUT_DIM)        // 2560
#define HID_OUT ((size_t)MROWS * HID)    // 26,214,400 floats (hidden section)

#define THRESH 0.9f
#define DECAY  0.6f

// ------------------------- scratch (device globals; no runtime allocs) ----
__device__ __nv_bfloat16 g_Xbf[(size_t)MROWS * IN_DIM];        // 40.1 MB
__device__ __nv_bfloat16 g_W1c[(size_t)2 * IN_DIM * HID];      // 3.2 MB (rows 0..783 = hi, 784..1567 = lo)
__device__ float         g_U1[(size_t)MROWS * HID];            // 104.9 MB
__device__ float         g_U2[(size_t)MROWS * OUT_DIM];        // 1.0 MB

// ------------------------- helpers ---------------------------------------
__device__ __forceinline__ void cpasync16(void* smem, const void* gmem) {
    uint32_t s = (uint32_t)__cvta_generic_to_shared(smem);
    asm volatile("cp.async.cg.shared.global [%0], [%1], 16;\n" :: "r"(s), "l"(gmem));
}

__device__ __forceinline__ void ldsm_x4(uint32_t& r0, uint32_t& r1, uint32_t& r2, uint32_t& r3, uint32_t addr) {
    asm volatile("ldmatrix.sync.aligned.m8n8.x4.shared.b16 {%0,%1,%2,%3}, [%4];\n"
                 : "=r"(r0), "=r"(r1), "=r"(r2), "=r"(r3) : "r"(addr));
}

__device__ __forceinline__ void ldsm_x4_t(uint32_t& r0, uint32_t& r1, uint32_t& r2, uint32_t& r3, uint32_t addr) {
    asm volatile("ldmatrix.sync.aligned.m8n8.x4.trans.shared.b16 {%0,%1,%2,%3}, [%4];\n"
                 : "=r"(r0), "=r"(r1), "=r"(r2), "=r"(r3) : "r"(addr));
}

__device__ __forceinline__ void mma16816(float* c, const uint32_t* a, uint32_t b0, uint32_t b1) {
    asm volatile(
        "mma.sync.aligned.m16n8k16.row.col.f32.bf16.bf16.f32 "
        "{%0,%1,%2,%3}, {%4,%5,%6,%7}, {%8,%9}, {%0,%1,%2,%3};\n"
        : "+f"(c[0]), "+f"(c[1]), "+f"(c[2]), "+f"(c[3])
        : "r"(a[0]), "r"(a[1]), "r"(a[2]), "r"(a[3]), "r"(b0), "r"(b1));
}

// ------------------------- prep kernels -----------------------------------
// X (float 0/1) -> bf16 (exact).  5,017,600 float4s.
__global__ void prep_x_kernel(const float4* __restrict__ x) {
    int i = blockIdx.x * blockDim.x + threadIdx.x;
    float4 v = x[i];
    __nv_bfloat162* dst = reinterpret_cast<__nv_bfloat162*>(g_Xbf);
    dst[2 * i]     = __floats2bfloat162_rn(v.x, v.y);
    dst[2 * i + 1] = __floats2bfloat162_rn(v.z, v.w);
}

// W1 (float [784,1024]) -> split hi/lo bf16 into combined [1568,1024]
__global__ void prep_w_kernel(const float* __restrict__ w1) {
    int i = blockIdx.x * blockDim.x + threadIdx.x;   // < 802816
    float w = w1[i];
    __nv_bfloat16 hi = __float2bfloat16(w);
    __nv_bfloat16 lo = __float2bfloat16(w - __bfloat162float(hi));
    g_W1c[i] = hi;
    g_W1c[802816 + i] = lo;
}

// ------------------------- GEMM1: U1 = X @ (W1hi + W1lo) ------------------
// Block tile 128x128, BK=16, 8 warps (2x4), warp tile 64x32.
// Both hi/lo passes share the A tile and accumulate into the same fp32 regs.
#define ASTRIDE 24    // padded bf16 per A row  (48B, conflict-free ldmatrix)
#define BSTRIDE 136   // padded bf16 per B row  (272B, conflict-free ldmatrix.trans)

__global__ __launch_bounds__(256, 2) void gemm1_kernel() {
    __shared__ __nv_bfloat16 sA[2][128][ASTRIDE];
    __shared__ __nv_bfloat16 sB[2][2][16][BSTRIDE];

    const int tid = threadIdx.x;
    const int bn0 = blockIdx.x * 128;
    const int bm0 = blockIdx.y * 128;

    const int lane   = tid & 31;
    const int wid    = tid >> 5;
    const int warp_m = wid >> 2;   // 0..1  (64 rows each)
    const int warp_n = wid & 3;    // 0..3  (32 cols each)

    float acc[4][4][4];
#pragma unroll
    for (int i = 0; i < 4; i++)
#pragma unroll
        for (int j = 0; j < 4; j++)
#pragma unroll
            for (int k = 0; k < 4; k++) acc[i][j][k] = 0.0f;

    // cp.async source addressing
    const int arow = tid >> 1;     // 0..127
    const int ach  = tid & 1;      // 2 x 16B chunks per 32B A row
    const __nv_bfloat16* agp = g_Xbf + (size_t)(bm0 + arow) * IN_DIM + ach * 8;

    const int brow = tid >> 4;     // 0..15
    const int bch  = tid & 15;     // 16 x 16B chunks per 256B B row
    const __nv_bfloat16* bgp = g_W1c + (size_t)brow * HID + bn0 + bch * 8;

#define LOAD_STAGE(st, kt) do {                                                   \
        cpasync16(&sA[st][arow][ach * 8], agp + (size_t)(kt) * 16);               \
        cpasync16(&sB[st][0][brow][bch * 8], bgp + (size_t)(kt) * 16 * HID);      \
        cpasync16(&sB[st][1][brow][bch * 8], bgp + 802816 + (size_t)(kt) * 16 * HID); \
        asm volatile("cp.async.commit_group;\n" ::: "memory");                    \
    } while (0)

    LOAD_STAGE(0, 0);

    for (int kt = 0; kt < 49; kt++) {
        const int cur = kt & 1;
        if (kt + 1 < 49) {
            LOAD_STAGE(cur ^ 1, kt + 1);
            asm volatile("cp.async.wait_group 1;\n" ::: "memory");
        } else {
            asm volatile("cp.async.wait_group 0;\n" ::: "memory");
        }
        __syncthreads();

        // A fragments (reused for both hi/lo passes)
        uint32_t a[4][4];
#pragma unroll
        for (int mt = 0; mt < 4; mt++) {
            int row = warp_m * 64 + mt * 16 + (lane & 15);
            uint32_t addr = (uint32_t)__cvta_generic_to_shared(&sA[cur][row][0]) + (lane >> 4) * 16;
            ldsm_x4(a[mt][0], a[mt][1], a[mt][2], a[mt][3], addr);
        }
#pragma unroll
        for (int p = 0; p < 2; p++) {
#pragma unroll
            for (int nt = 0; nt < 2; nt++) {
                uint32_t b0, b1, b2, b3;
                int krow = lane & 15;
                int col  = warp_n * 32 + nt * 16 + (lane >> 4) * 8;
                uint32_t addr = (uint32_t)__cvta_generic_to_shared(&sB[cur][p][krow][col]);
                ldsm_x4_t(b0, b1, b2, b3, addr);
#pragma unroll
                for (int mt = 0; mt < 4; mt++) {
                    mma16816(acc[mt][nt * 2],     a[mt], b0, b1);
                    mma16816(acc[mt][nt * 2 + 1], a[mt], b2, b3);
                }
            }
        }
        __syncthreads();
    }

    // epilogue: write U1 (fp32)
    const int g  = lane >> 2;
    const int tg = lane & 3;
#pragma unroll
    for (int mt = 0; mt < 4; mt++) {
        int m0 = bm0 + warp_m * 64 + mt * 16 + g;
#pragma unroll
        for (int nf = 0; nf < 4; nf++) {
            int n0 = bn0 + warp_n * 32 + nf * 8 + tg * 2;
            float2 v0 = make_float2(acc[mt][nf][0], acc[mt][nf][1]);
            float2 v1 = make_float2(acc[mt][nf][2], acc[mt][nf][3]);
            *(float2*)&g_U1[(size_t)m0 * HID + n0]       = v0;
            *(float2*)&g_U1[(size_t)(m0 + 8) * HID + n0] = v1;
        }
    }
#undef LOAD_STAGE
}

// ------------------------- scan1: LIF over hidden layer -------------------
// One thread per (b,h); fully coalesced over h. Writes spikes into d_out.
__global__ void scan1_kernel(float* __restrict__ out) {
    const int idx = blockIdx.x * blockDim.x + threadIdx.x;  // 0..262143
    float mem = 0.0f;
#pragma unroll 5
    for (int t = 0; t < T_STEPS; t++) {
        float u = g_U1[(size_t)t * BH + idx];
        mem = mem * DECAY + u;
        float s = (mem >= THRESH) ? 1.0f : 0.0f;
        mem -= s * THRESH;
        out[(size_t)t * BH + idx] = s;
    }
}

// ------------------------- GEMM2: U2 = Hs @ W2 ----------------------------
// One warp per (t,b) row. Spikes are exactly 1.0f -> branch-skip add of W2 rows.
__global__ void gemm2_kernel(const float* __restrict__ hs, const float* __restrict__ W2) {
    const int gw   = (blockIdx.x * blockDim.x + threadIdx.x) >> 5;  // 0..25599
    const int lane = threadIdx.x & 31;
    const float* row = hs + (size_t)gw * HID;
    float acc[OUT_DIM];
#pragma unroll
    for (int o = 0; o < OUT_DIM; o++) acc[o] = 0.0f;
    for (int k = lane; k < HID; k += 32) {
        if (row[k] != 0.0f) {
            const float* w = W2 + k * OUT_DIM;
#pragma unroll
            for (int o = 0; o < OUT_DIM; o++) acc[o] += w[o];
        }
    }
#pragma unroll
    for (int o = 0; o < OUT_DIM; o++) {
#pragma unroll
        for (int off = 16; off > 0; off >>= 1)
            acc[o] += __shfl_xor_sync(0xffffffffu, acc[o], off);
    }
    if (lane == 0) {
#pragma unroll
        for (int o = 0; o < OUT_DIM; o++) g_U2[(size_t)gw * OUT_DIM + o] = acc[o];
    }
}

// ------------------------- scan2: LIF over output layer -------------------
__global__ void scan2_kernel(float* __restrict__ out2) {
    const int idx = blockIdx.x * blockDim.x + threadIdx.x;  // 0..2559
    if (idx >= BO) return;
    float mem = 0.0f;
#pragma unroll 5
    for (int t = 0; t < T_STEPS; t++) {
        float u = g_U2[(size_t)t * BO + idx];
        mem = mem * DECAY + u;
        float s = (mem >= THRESH) ? 1.0f : 0.0f;
        mem -= s * THRESH;
        out2[(size_t)t * BO + idx] = s;
    }
}

// ------------------------- launch -----------------------------------------
extern "C" void kernel_launch(void* const* d_in, const int* in_sizes, int n_in,
                              void* d_out, int out_size) {
    const float* X  = (const float*)d_in[0];   // [100,256,784]
    const float* W1 = (const float*)d_in[1];   // [784,1024]
    const float* W2 = (const float*)d_in[2];   // [1024,10]
    float* out = (float*)d_out;                // hidden spikes then output spikes

    (void)in_sizes; (void)n_in; (void)out_size;

    prep_x_kernel<<<19600, 256>>>((const float4*)X);   // 5,017,600 float4
    prep_w_kernel<<<3136, 256>>>(W1);                  // 802,816

    dim3 g1(HID / 128, MROWS / 128);                   // (8, 200)
    gemm1_kernel<<<g1, 256>>>();

    scan1_kernel<<<BH / 256, 256>>>(out);              // 1024 blocks

    gemm2_kernel<<<MROWS / 8, 256>>>(out, W2);         // 3200 blocks, 8 warps each

    scan2_kernel<<<10, 256>>>(out + HID_OUT);          // 2560 threads
}

// round 3
// speedup vs baseline: 1.0644x; 1.0644x over previous
#include <cuda_runtime.h>
#include <cuda_bf16.h>
#include <cstdint>
#include <cstddef>

// Problem dims (fixed)
#define T_STEPS 100
#define BATCH   256
#define IN_DIM  784
#define HID     1024
#define OUT_DIM 10
#define MROWS   25600
#define BH      262144
#define BO      2560
#define HID_OUT ((size_t)MROWS * HID)
#define THRESH 0.9f
#define DECAY  0.6f

// GEMM1 tiling: 128x128 CTA tile, BK=16, 49 k-iters, 5-stage cp.async ring
#define NKIT 49
#define NSTAGE 5
#define A_STAGE_B 6144u     // 128 rows * 24 bf16 (48B, padded)
#define B_PLANE_B 4352u     // 16 rows * 136 bf16 (272B, padded)
#define STAGE_B  14848u     // A + 2 B planes
#define SMEM_TOTAL (NSTAGE * STAGE_B)   // 74240

// ------------------------- scratch (device globals) -----------------------
__device__ __nv_bfloat16 g_Xbf[(size_t)MROWS * IN_DIM];        // 40.1 MB
__device__ __nv_bfloat16 g_W1c[(size_t)2 * IN_DIM * HID];      // hi rows 0..783, lo rows 784..1567
__device__ float         g_U1[(size_t)MROWS * HID];            // 104.9 MB
__device__ float         g_U2[(size_t)MROWS * OUT_DIM];        // 1.0 MB

// ------------------------- helpers ---------------------------------------
__device__ __forceinline__ uint32_t smem_u32(const void* p) {
    uint32_t a;
    asm("{ .reg .u64 t; cvta.to.shared.u64 t, %1; cvt.u32.u64 %0, t; }" : "=r"(a) : "l"(p));
    return a;
}
__device__ __forceinline__ void cpa16(uint32_t s, const void* g) {
    asm volatile("cp.async.cg.shared.global [%0], [%1], 16;\n" :: "r"(s), "l"(g));
}
__device__ __forceinline__ void ldsm_x4(uint32_t& r0, uint32_t& r1, uint32_t& r2, uint32_t& r3, uint32_t addr) {
    asm volatile("ldmatrix.sync.aligned.m8n8.x4.shared.b16 {%0,%1,%2,%3}, [%4];\n"
                 : "=r"(r0), "=r"(r1), "=r"(r2), "=r"(r3) : "r"(addr));
}
__device__ __forceinline__ void ldsm_x4_t(uint32_t& r0, uint32_t& r1, uint32_t& r2, uint32_t& r3, uint32_t addr) {
    asm volatile("ldmatrix.sync.aligned.m8n8.x4.trans.shared.b16 {%0,%1,%2,%3}, [%4];\n"
                 : "=r"(r0), "=r"(r1), "=r"(r2), "=r"(r3) : "r"(addr));
}
__device__ __forceinline__ void mma16816(float* c, const uint32_t* a, uint32_t b0, uint32_t b1) {
    asm volatile(
        "mma.sync.aligned.m16n8k16.row.col.f32.bf16.bf16.f32 "
        "{%0,%1,%2,%3}, {%4,%5,%6,%7}, {%8,%9}, {%0,%1,%2,%3};\n"
        : "+f"(c[0]), "+f"(c[1]), "+f"(c[2]), "+f"(c[3])
        : "r"(a[0]), "r"(a[1]), "r"(a[2]), "r"(a[3]), "r"(b0), "r"(b1));
}

// ------------------------- prep kernels -----------------------------------
__global__ void prep_x_kernel(const float4* __restrict__ x) {
    int i = blockIdx.x * blockDim.x + threadIdx.x;     // < 5,017,600
    float4 v = x[i];
    __nv_bfloat162* dst = reinterpret_cast<__nv_bfloat162*>(g_Xbf);
    dst[2 * i]     = __floats2bfloat162_rn(v.x, v.y);
    dst[2 * i + 1] = __floats2bfloat162_rn(v.z, v.w);
}

__global__ void prep_w_kernel(const float* __restrict__ w1) {
    int i = blockIdx.x * blockDim.x + threadIdx.x;     // < 802816
    float w = w1[i];
    __nv_bfloat16 hi = __float2bfloat16(w);
    __nv_bfloat16 lo = __float2bfloat16(w - __bfloat162float(hi));
    g_W1c[i] = hi;
    g_W1c[802816 + i] = lo;
}

__global__ void zero_u2_kernel() {
    int i = blockIdx.x * blockDim.x + threadIdx.x;     // < 64000
    reinterpret_cast<float4*>(g_U2)[i] = make_float4(0.f, 0.f, 0.f, 0.f);
}

// ------------------------- GEMM1: U1 = X @ (W1hi + W1lo) ------------------
// 8 warps (2x4), warp tile 64x32, fp32 accum; hi/lo passes share the A tile.
__global__ __launch_bounds__(256, 2) void gemm1_kernel() {
    extern __shared__ char smem[];
    const uint32_t sbase = smem_u32(smem);

    const int tid = threadIdx.x;
    const int bn0 = blockIdx.x * 128;
    const int bm0 = blockIdx.y * 128;

    const int lane   = tid & 31;
    const int wid    = tid >> 5;
    const int warp_m = wid >> 2;   // 0..1
    const int warp_n = wid & 3;    // 0..3

    float acc[4][4][4];
#pragma unroll
    for (int i = 0; i < 4; i++)
#pragma unroll
        for (int j = 0; j < 4; j++)
#pragma unroll
            for (int k = 0; k < 4; k++) acc[i][j][k] = 0.0f;

    // producer addressing
    const int arow = tid >> 1, ach = tid & 1;
    const __nv_bfloat16* agp = g_Xbf + (size_t)(bm0 + arow) * IN_DIM + ach * 8;
    const int brow = tid >> 4, bch = tid & 15;
    const __nv_bfloat16* bgp = g_W1c + (size_t)brow * HID + bn0 + bch * 8;

    const uint32_t a_dst = sbase + arow * 48 + ach * 16;
    const uint32_t b_dst = sbase + A_STAGE_B + brow * 272 + bch * 16;

#define LOAD_STAGE(slot, kt) do {                                                   \
        uint32_t so = (slot) * STAGE_B;                                             \
        const __nv_bfloat16* a = agp + (size_t)(kt) * 16;                           \
        const __nv_bfloat16* b = bgp + (size_t)(kt) * 16 * HID;                     \
        cpa16(a_dst + so, a);                                                       \
        cpa16(b_dst + so, b);                                                       \
        cpa16(b_dst + so + B_PLANE_B, b + 802816);                                  \
        asm volatile("cp.async.commit_group;\n" ::: "memory");                      \
    } while (0)

    LOAD_STAGE(0, 0);
    LOAD_STAGE(1, 1);
    LOAD_STAGE(2, 2);
    LOAD_STAGE(3, 3);

    for (int kt = 0; kt < NKIT; kt++) {
        const int cur = kt % NSTAGE;
        asm volatile("cp.async.wait_group 3;\n" ::: "memory");
        __syncthreads();

        // prefetch 4 ahead into the slot consumed last iteration
        if (kt + 4 < NKIT) {
            LOAD_STAGE((kt + 4) % NSTAGE, kt + 4);
        } else {
            asm volatile("cp.async.commit_group;\n" ::: "memory");
        }

        const uint32_t so = sbase + cur * STAGE_B;

        // A fragments (shared by hi/lo passes)
        uint32_t a[4][4];
#pragma unroll
        for (int mt = 0; mt < 4; mt++) {
            int row = warp_m * 64 + mt * 16 + (lane & 15);
            uint32_t addr = so + row * 48 + (lane >> 4) * 16;
            ldsm_x4(a[mt][0], a[mt][1], a[mt][2], a[mt][3], addr);
        }
#pragma unroll
        for (int p = 0; p < 2; p++) {
#pragma unroll
            for (int nt = 0; nt < 2; nt++) {
                uint32_t b0, b1, b2, b3;
                int krow = lane & 15;
                int col  = warp_n * 32 + nt * 16 + (lane >> 4) * 8;
                uint32_t addr = so + A_STAGE_B + p * B_PLANE_B + krow * 272 + col * 2;
                ldsm_x4_t(b0, b1, b2, b3, addr);
#pragma unroll
                for (int mt = 0; mt < 4; mt++) {
                    mma16816(acc[mt][nt * 2],     a[mt], b0, b1);
                    mma16816(acc[mt][nt * 2 + 1], a[mt], b2, b3);
                }
            }
        }
    }
#undef LOAD_STAGE

    // epilogue: write U1 (fp32)
    const int g  = lane >> 2;
    const int tg = lane & 3;
#pragma unroll
    for (int mt = 0; mt < 4; mt++) {
        int m0 = bm0 + warp_m * 64 + mt * 16 + g;
#pragma unroll
        for (int nf = 0; nf < 4; nf++) {
            int n0 = bn0 + warp_n * 32 + nf * 8 + tg * 2;
            float2 v0 = make_float2(acc[mt][nf][0], acc[mt][nf][1]);
            float2 v1 = make_float2(acc[mt][nf][2], acc[mt][nf][3]);
            *(float2*)&g_U1[(size_t)m0 * HID + n0]       = v0;
            *(float2*)&g_U1[(size_t)(m0 + 8) * HID + n0] = v1;
        }
    }
}

// ---------------- scan1: LIF hidden + fused sparse GEMM2 ------------------
// One thread per 4 (b,h) lanes. On the (rare) spike, scatter W2 row into U2.
__global__ void scan1_kernel(float4* __restrict__ out, const float* __restrict__ W2) {
    const int idx = blockIdx.x * blockDim.x + threadIdx.x;   // 0..65535
    const float4* u = reinterpret_cast<const float4*>(g_U1);
    const int j0 = idx * 4;
    const int b  = j0 >> 10;
    const int h0 = j0 & 1023;
    float4 mem = make_float4(0.f, 0.f, 0.f, 0.f);
#pragma unroll 4
    for (int t = 0; t < T_STEPS; t++) {
        float4 v = __ldcg(&u[(size_t)t * (BH / 4) + idx]);
        float4 s;
        mem.x = mem.x * DECAY + v.x; s.x = (mem.x >= THRESH) ? 1.f : 0.f; mem.x -= s.x * THRESH;
        mem.y = mem.y * DECAY + v.y; s.y = (mem.y >= THRESH) ? 1.f : 0.f; mem.y -= s.y * THRESH;
        mem.z = mem.z * DECAY + v.z; s.z = (mem.z >= THRESH) ? 1.f : 0.f; mem.z -= s.z * THRESH;
        mem.w = mem.w * DECAY + v.w; s.w = (mem.w >= THRESH) ? 1.f : 0.f; mem.w -= s.w * THRESH;
        out[(size_t)t * (BH / 4) + idx] = s;
        if (s.x + s.y + s.z + s.w > 0.f) {     // extremely rare
            float sv[4] = {s.x, s.y, s.z, s.w};
            float* u2 = g_U2 + (size_t)(t * BATCH + b) * OUT_DIM;
#pragma unroll
            for (int q = 0; q < 4; q++) {
                if (sv[q] != 0.f) {
                    const float* w = W2 + (h0 + q) * OUT_DIM;
#pragma unroll
                    for (int o = 0; o < OUT_DIM; o++) atomicAdd(&u2[o], w[o]);
                }
            }
        }
    }
}

// ------------------------- scan2 ------------------------------------------
__global__ void scan2_kernel(float* __restrict__ out2) {
    const int idx = blockIdx.x * blockDim.x + threadIdx.x;
    if (idx >= BO) return;
    float mem = 0.0f;
#pragma unroll 5
    for (int t = 0; t < T_STEPS; t++) {
        float u = g_U2[(size_t)t * BO + idx];
        mem = mem * DECAY + u;
        float s = (mem >= THRESH) ? 1.0f : 0.0f;
        mem -= s * THRESH;
        out2[(size_t)t * BO + idx] = s;
    }
}

// ------------------------- launch ------------------------------------------
extern "C" void kernel_launch(void* const* d_in, const int* in_sizes, int n_in,
                              void* d_out, int out_size) {
    const float* X  = (const float*)d_in[0];
    const float* W1 = (const float*)d_in[1];
    const float* W2 = (const float*)d_in[2];
    float* out = (float*)d_out;
    (void)in_sizes; (void)n_in; (void)out_size;

    static bool attr_done = false;
    if (!attr_done) {
        cudaFuncSetAttribute(gemm1_kernel, cudaFuncAttributeMaxDynamicSharedMemorySize, SMEM_TOTAL);
        attr_done = true;
    }

    prep_x_kernel<<<19600, 256>>>((const float4*)X);
    prep_w_kernel<<<3136, 256>>>(W1);
    zero_u2_kernel<<<250, 256>>>();

    gemm1_kernel<<<dim3(8, 200), 256, SMEM_TOTAL>>>();

    scan1_kernel<<<256, 256>>>((float4*)out, W2);

    scan2_kernel<<<10, 256>>>(out + HID_OUT);
}